// round 3
// baseline (speedup 1.0000x reference)
#include <cuda_runtime.h>
#include <cuda_fp16.h>
#include <cstdint>

// ============================================================================
// ModulatedConv1d (B=16, C=512, L=2048, K=3, pad=1)  — plain sm_100 path
//   s[b,i]    = MOD_SCALE * style[b,:] @ modW[i,:] + bias[i]
//   gain[b,o] = SCALE * rsqrt(SCALE^2 * sum_i s^2 * wsq[o,i] + 1e-8)
//   out[b,o,l]= gain[b,o] * sum_{i,k} W[o,i,k] * s[b,i] * x[b,i,l+k-1]
// Core GEMM: mma.sync.m16n8k16 f16 -> f32. CTA tile 128(o) x 256(l), K=1536.
// ============================================================================

#define MOD_SCALE_F 0.04419417382415922f   /* 1/sqrt(512)   */
#define SCALE_F     0.014731391274719739f  /* 1/sqrt(512*9) */

#define NTHREADS 512
// SMEM stage layout (per buffer):
//   A: 3 taps x 128 o-rows x 80B (32 halves + pad)  = 30720B
//   X: 258 l-rows x 80B (32 halves + pad)           = 20640B
#define A_TAP   10240
#define X_OFF   30720
#define STAGE   51360
#define SMEM_TOTAL (2 * STAGE)

// scratch (static device arrays; no runtime allocation)
__device__ float  g_s[16 * 512];
__device__ float  g_wsq[512 * 512];
__device__ float  g_gain[16 * 512];
__device__ __half g_wh[3 * 512 * 512];   // [k][o][i], fp16

// ---------------------------------------------------------------------------
__device__ __forceinline__ void cp_async16(void* smem_dst, const void* gsrc) {
    uint32_t a;
    asm("{ .reg .u64 t; cvta.to.shared.u64 t, %1; cvt.u32.u64 %0, t; }" : "=r"(a) : "l"(smem_dst));
    asm volatile("cp.async.cg.shared.global [%0], [%1], 16;" :: "r"(a), "l"(gsrc));
}
__device__ __forceinline__ void cp_async_commit() {
    asm volatile("cp.async.commit_group;");
}
__device__ __forceinline__ void cp_async_wait0() {
    asm volatile("cp.async.wait_group 0;" ::: "memory");
}

__device__ __forceinline__ void mma_f16(float* c, const uint32_t* a, uint32_t b0, uint32_t b1) {
    asm volatile(
        "mma.sync.aligned.m16n8k16.row.col.f32.f16.f16.f32 "
        "{%0,%1,%2,%3}, {%4,%5,%6,%7}, {%8,%9}, {%0,%1,%2,%3};"
        : "+f"(c[0]), "+f"(c[1]), "+f"(c[2]), "+f"(c[3])
        : "r"(a[0]), "r"(a[1]), "r"(a[2]), "r"(a[3]), "r"(b0), "r"(b1));
}

// ---------------------------------------------------------------------------
// Prep kernels
// ---------------------------------------------------------------------------
__global__ void prep_w(const float* __restrict__ w) {
    int idx = blockIdx.x * 256 + threadIdx.x;  // idx = o*512 + i, grid 1024
    float w0 = w[idx * 3 + 0];
    float w1 = w[idx * 3 + 1];
    float w2 = w[idx * 3 + 2];
    g_wh[0 * 262144 + idx] = __float2half_rn(w0);
    g_wh[1 * 262144 + idx] = __float2half_rn(w1);
    g_wh[2 * 262144 + idx] = __float2half_rn(w2);
    g_wsq[idx] = w0 * w0 + w1 * w1 + w2 * w2;
}

__global__ void prep_s(const float* __restrict__ style, const float* __restrict__ modw,
                       const float* __restrict__ bias) {
    __shared__ float st[512];
    int b = blockIdx.x, chunk = blockIdx.y;  // grid (16, 8)
    for (int i = threadIdx.x; i < 512; i += 256) st[i] = style[b * 512 + i];
    __syncthreads();
    int warp = threadIdx.x >> 5, lane = threadIdx.x & 31;
    for (int it = 0; it < 8; it++) {
        int i = chunk * 64 + it * 8 + warp;
        const float* mrow = modw + (size_t)i * 512;
        float acc = 0.f;
        #pragma unroll
        for (int t = 0; t < 16; t++) acc += mrow[lane + t * 32] * st[lane + t * 32];
        #pragma unroll
        for (int o = 16; o; o >>= 1) acc += __shfl_xor_sync(0xFFFFFFFFu, acc, o);
        if (lane == 0) g_s[b * 512 + i] = acc * MOD_SCALE_F + bias[i];
    }
}

__global__ void prep_gain() {
    __shared__ float s2[512];
    int b = blockIdx.x, chunk = blockIdx.y;  // grid (16, 8)
    for (int i = threadIdx.x; i < 512; i += 256) {
        float v = g_s[b * 512 + i];
        s2[i] = v * v;
    }
    __syncthreads();
    int warp = threadIdx.x >> 5, lane = threadIdx.x & 31;
    for (int it = 0; it < 8; it++) {
        int o = chunk * 64 + it * 8 + warp;
        const float* wr = g_wsq + (size_t)o * 512;
        float acc = 0.f;
        #pragma unroll
        for (int t = 0; t < 16; t++) acc += wr[lane + t * 32] * s2[lane + t * 32];
        #pragma unroll
        for (int off = 16; off; off >>= 1) acc += __shfl_xor_sync(0xFFFFFFFFu, acc, off);
        if (lane == 0)
            g_gain[b * 512 + o] = SCALE_F * rsqrtf(SCALE_F * SCALE_F * acc + 1e-8f);
    }
}

// ---------------------------------------------------------------------------
// Main kernel: 512 CTAs = 4 o-tiles x 8 l-tiles x 16 b; 512 threads.
// Warp grid 4(m) x 4(n): warp tile 32(o) x 64(l). 16 chunks of K=32 (x3 taps).
// ---------------------------------------------------------------------------
__global__ void __launch_bounds__(NTHREADS, 1)
conv_main(const float* __restrict__ x, float* __restrict__ out) {
    extern __shared__ char smem[];
    __shared__ float s_sh[512];

    const int tid  = threadIdx.x;
    const int warp = tid >> 5;
    const int lane = tid & 31;
    const int mw32 = (warp & 3) * 32;     // warp m-offset
    const int nw64 = (warp >> 2) * 64;    // warp n-offset

    const int bx    = blockIdx.x;
    const int obase = (bx & 3) * 128;
    const int l0    = ((bx >> 2) & 7) * 256;
    const int b     = bx >> 5;

    const float* xb = x + (size_t)b * 512 * 2048;

    // stage s into shared
    for (int i = tid; i < 512; i += NTHREADS) s_sh[i] = g_s[b * 512 + i];
    __syncthreads();

    // per-thread X-load geometry: fixed i-lane, rows vary
    const int il = tid & 31;              // i within chunk
    const int qw = tid >> 5;              // 0..15

    float acc[2][8][4];
    #pragma unroll
    for (int mi = 0; mi < 2; mi++)
        #pragma unroll
        for (int ni = 0; ni < 8; ni++)
            #pragma unroll
            for (int j = 0; j < 4; j++) acc[mi][ni][j] = 0.f;

    // ---- stage loader pieces ----
    auto issue_w = [&](int ic, char* buf) {
        // A: 3 taps x 128 x 32 halves; one 16B cp.async per (tap); thread -> (o=tid>>2, c=tid&3)
        int o = tid >> 2, c = tid & 3;
        #pragma unroll
        for (int t = 0; t < 3; t++) {
            const __half* src = g_wh + (size_t)t * 262144 + (size_t)(obase + o) * 512 + ic * 32 + c * 8;
            cp_async16(buf + t * A_TAP + o * 80 + c * 16, src);
        }
        cp_async_commit();
    };

    // main X: 4 float4 per thread (i = il, l-quads qw + p*16)
    auto issue_x = [&](int ic, float4* f4, float* edge) {
        const float* xrow = xb + (size_t)(ic * 32 + il) * 2048 + l0;
        const float4* xr4 = (const float4*)xrow;
        #pragma unroll
        for (int p = 0; p < 4; p++) f4[p] = xr4[qw + p * 16];
        // edge rows: threads 0..31 -> row 0 (l0-1), threads 32..63 -> row 257 (l0+256)
        if (tid < 64) {
            const float* xe = xb + (size_t)(ic * 32 + il) * 2048;
            if (tid < 32) *edge = (l0 > 0) ? xe[l0 - 1] : 0.f;
            else          *edge = (l0 + 256 < 2048) ? xe[l0 + 256] : 0.f;
        }
    };

    auto finish_x = [&](int ic, char* buf, const float4* f4, float edge) {
        const float sv = s_sh[ic * 32 + il];
        char* Xb = buf + X_OFF;
        #pragma unroll
        for (int p = 0; p < 4; p++) {
            int r = 1 + (qw + p * 16) * 4;
            *(__half*)(Xb + (r + 0) * 80 + il * 2) = __float2half_rn(f4[p].x * sv);
            *(__half*)(Xb + (r + 1) * 80 + il * 2) = __float2half_rn(f4[p].y * sv);
            *(__half*)(Xb + (r + 2) * 80 + il * 2) = __float2half_rn(f4[p].z * sv);
            *(__half*)(Xb + (r + 3) * 80 + il * 2) = __float2half_rn(f4[p].w * sv);
        }
        if (tid < 64) {
            int r = (tid < 32) ? 0 : 257;
            *(__half*)(Xb + r * 80 + il * 2) = __float2half_rn(edge * sv);
        }
    };

    // ---- prologue: chunk 0 into buffer 0 ----
    {
        float4 f4[4]; float edge = 0.f;
        issue_x(0, f4, &edge);
        issue_w(0, smem);
        finish_x(0, smem, f4, edge);
        cp_async_wait0();
    }
    __syncthreads();

    // ---- main loop over 16 i-chunks ----
    for (int ic = 0; ic < 16; ic++) {
        char* buf = smem + (ic & 1) * STAGE;
        char* nxt = smem + ((ic & 1) ^ 1) * STAGE;

        float4 f4[4]; float edge = 0.f;
        if (ic < 15) {
            issue_x(ic + 1, f4, &edge);
            issue_w(ic + 1, nxt);
        }

        // ---- compute: 3 taps x 2 k16 steps, 16 mma each ----
        #pragma unroll
        for (int t = 0; t < 3; t++) {
            #pragma unroll
            for (int ks = 0; ks < 2; ks++) {
                const int kh = ks * 16 + (lane & 3) * 2;   // k half-index
                // A fragments (2 m16 tiles)
                const char* ka = buf + t * A_TAP + (mw32 + (lane >> 2)) * 80 + kh * 2;
                uint32_t a[2][4];
                #pragma unroll
                for (int mi = 0; mi < 2; mi++) {
                    const char* p = ka + mi * (16 * 80);
                    a[mi][0] = *(const uint32_t*)(p);
                    a[mi][1] = *(const uint32_t*)(p + 8 * 80);
                    a[mi][2] = *(const uint32_t*)(p + 16);
                    a[mi][3] = *(const uint32_t*)(p + 8 * 80 + 16);
                }
                // B fragments (8 n8 tiles), row-shifted by tap t
                const char* kb = buf + X_OFF + (nw64 + (lane >> 2) + t) * 80 + kh * 2;
                #pragma unroll
                for (int ni = 0; ni < 8; ni++) {
                    uint32_t b0 = *(const uint32_t*)(kb + ni * (8 * 80));
                    uint32_t b1 = *(const uint32_t*)(kb + ni * (8 * 80) + 16);
                    mma_f16(acc[0][ni], a[0], b0, b1);
                    mma_f16(acc[1][ni], a[1], b0, b1);
                }
            }
        }

        if (ic < 15) {
            finish_x(ic + 1, nxt, f4, edge);
            cp_async_wait0();
        }
        __syncthreads();
    }

    // ---- epilogue: apply gain, store ----
    {
        const int r0 = obase + mw32 + (lane >> 2);
        const float g00 = g_gain[b * 512 + r0];
        const float g01 = g_gain[b * 512 + r0 + 8];
        const float g10 = g_gain[b * 512 + r0 + 16];
        const float g11 = g_gain[b * 512 + r0 + 24];
        const int lcol = l0 + nw64 + (lane & 3) * 2;

        #pragma unroll
        for (int mi = 0; mi < 2; mi++) {
            const int ra = r0 + mi * 16;
            const float ga = mi ? g10 : g00;
            const float gb = mi ? g11 : g01;
            float* outa = out + ((size_t)(b * 512 + ra)) * 2048 + lcol;
            float* outb = out + ((size_t)(b * 512 + ra + 8)) * 2048 + lcol;
            #pragma unroll
            for (int ni = 0; ni < 8; ni++) {
                float2 va, vb;
                va.x = acc[mi][ni][0] * ga;
                va.y = acc[mi][ni][1] * ga;
                vb.x = acc[mi][ni][2] * gb;
                vb.y = acc[mi][ni][3] * gb;
                *(float2*)(outa + ni * 8) = va;
                *(float2*)(outb + ni * 8) = vb;
            }
        }
    }
}

// ---------------------------------------------------------------------------
extern "C" void kernel_launch(void* const* d_in, const int* in_sizes, int n_in,
                              void* d_out, int out_size) {
    const float* x      = (const float*)d_in[0];
    const float* style  = (const float*)d_in[1];
    const float* weight = (const float*)d_in[2];
    const float* modw   = (const float*)d_in[3];
    const float* bias   = (const float*)d_in[4];
    float* out = (float*)d_out;

    cudaFuncSetAttribute(conv_main, cudaFuncAttributeMaxDynamicSharedMemorySize, SMEM_TOTAL);

    prep_w<<<1024, 256>>>(weight);
    prep_s<<<dim3(16, 8), 256>>>(style, modw, bias);
    prep_gain<<<dim3(16, 8), 256>>>();
    conv_main<<<512, NTHREADS, SMEM_TOTAL>>>(x, out);
}

// round 4
// speedup vs baseline: 1.4272x; 1.4272x over previous
#include <cuda_runtime.h>
#include <cuda_fp16.h>
#include <cstdint>

// ============================================================================
// ModulatedConv1d (B=16, C=512, L=2048, K=3, pad=1) — plain sm_100 path
//   s[b,i]    = MOD_SCALE * style[b,:] @ modW[i,:] + bias[i]
//   gain[b,o] = SCALE * rsqrt(SCALE^2 * sum_i s^2 * wsq[o,i] + 1e-8)
//   out[b,o,l]= gain[b,o] * sum_{i,k} W[o,i,k] * s[b,i] * x[b,i,l+k-1]
// Pre-pass builds x_t[b][l][i] = fp16(s*x); main GEMM = mma.m16n8k16 f16->f32,
// CTA tile 128(o) x 128(l), cp.async feeds, ldmatrix fragments, 2 CTAs/SM.
// ============================================================================

#define MOD_SCALE_F 0.04419417382415922f   /* 1/sqrt(512)   */
#define SCALE_F     0.014731391274719739f  /* 1/sqrt(512*9) */

#define NTHREADS 256
// Stage layout: A = 3 taps x 128 rows x 80B = 30720; X = 130 rows x 80B = 10400
#define A_TAP 10240
#define X_OFF 30720
#define STAGE 41120
#define SMEM_TOTAL (2 * STAGE)

// static device scratch (no runtime allocation)
__device__ float  g_s[16 * 512];
__device__ float  g_wsq[512 * 512];
__device__ float  g_gain[16 * 512];
__device__ __half g_wh[3 * 512 * 512];        // [k][o][i], fp16
__device__ __half g_xt[16 * 2048 * 512];      // [b][l][i] = fp16(s*x)

// ---------------------------------------------------------------------------
__device__ __forceinline__ uint32_t smem_u32(const void* p) {
    uint32_t a;
    asm("{ .reg .u64 t; cvta.to.shared.u64 t, %1; cvt.u32.u64 %0, t; }" : "=r"(a) : "l"(p));
    return a;
}
__device__ __forceinline__ void cp16(uint32_t dst, const void* src) {
    asm volatile("cp.async.cg.shared.global [%0], [%1], 16;" :: "r"(dst), "l"(src));
}
__device__ __forceinline__ void cp16z(uint32_t dst, const void* src, int szcp) {
    // szcp = 16 (copy) or 0 (zero-fill, no gmem access)
    asm volatile("cp.async.cg.shared.global [%0], [%1], 16, %2;" :: "r"(dst), "l"(src), "r"(szcp));
}
__device__ __forceinline__ void ldsm4(uint32_t* r, uint32_t addr) {
    asm volatile("ldmatrix.sync.aligned.m8n8.x4.shared.b16 {%0,%1,%2,%3}, [%4];"
        : "=r"(r[0]), "=r"(r[1]), "=r"(r[2]), "=r"(r[3]) : "r"(addr));
}
__device__ __forceinline__ void mma_f16(float* c, const uint32_t* a, uint32_t b0, uint32_t b1) {
    asm volatile(
        "mma.sync.aligned.m16n8k16.row.col.f32.f16.f16.f32 "
        "{%0,%1,%2,%3}, {%4,%5,%6,%7}, {%8,%9}, {%0,%1,%2,%3};"
        : "+f"(c[0]), "+f"(c[1]), "+f"(c[2]), "+f"(c[3])
        : "r"(a[0]), "r"(a[1]), "r"(a[2]), "r"(a[3]), "r"(b0), "r"(b1));
}

// ---------------------------------------------------------------------------
// Prep kernels
// ---------------------------------------------------------------------------
__global__ void prep_w(const float* __restrict__ w) {
    int idx = blockIdx.x * 256 + threadIdx.x;  // idx = o*512 + i, grid 1024
    float w0 = w[idx * 3 + 0];
    float w1 = w[idx * 3 + 1];
    float w2 = w[idx * 3 + 2];
    g_wh[0 * 262144 + idx] = __float2half_rn(w0);
    g_wh[1 * 262144 + idx] = __float2half_rn(w1);
    g_wh[2 * 262144 + idx] = __float2half_rn(w2);
    g_wsq[idx] = w0 * w0 + w1 * w1 + w2 * w2;
}

__global__ void prep_s(const float* __restrict__ style, const float* __restrict__ modw,
                       const float* __restrict__ bias) {
    __shared__ float st[512];
    int b = blockIdx.x, chunk = blockIdx.y;  // grid (16, 8)
    for (int i = threadIdx.x; i < 512; i += 256) st[i] = style[b * 512 + i];
    __syncthreads();
    int warp = threadIdx.x >> 5, lane = threadIdx.x & 31;
    for (int it = 0; it < 8; it++) {
        int i = chunk * 64 + it * 8 + warp;
        const float* mrow = modw + (size_t)i * 512;
        float acc = 0.f;
        #pragma unroll
        for (int t = 0; t < 16; t++) acc += mrow[lane + t * 32] * st[lane + t * 32];
        #pragma unroll
        for (int o = 16; o; o >>= 1) acc += __shfl_xor_sync(0xFFFFFFFFu, acc, o);
        if (lane == 0) g_s[b * 512 + i] = acc * MOD_SCALE_F + bias[i];
    }
}

__global__ void prep_gain() {
    __shared__ float s2[512];
    int b = blockIdx.x, chunk = blockIdx.y;  // grid (16, 8)
    for (int i = threadIdx.x; i < 512; i += 256) {
        float v = g_s[b * 512 + i];
        s2[i] = v * v;
    }
    __syncthreads();
    int warp = threadIdx.x >> 5, lane = threadIdx.x & 31;
    for (int it = 0; it < 8; it++) {
        int o = chunk * 64 + it * 8 + warp;
        const float* wr = g_wsq + (size_t)o * 512;
        float acc = 0.f;
        #pragma unroll
        for (int t = 0; t < 16; t++) acc += wr[lane + t * 32] * s2[lane + t * 32];
        #pragma unroll
        for (int off = 16; off; off >>= 1) acc += __shfl_xor_sync(0xFFFFFFFFu, acc, off);
        if (lane == 0)
            g_gain[b * 512 + o] = SCALE_F * rsqrtf(SCALE_F * SCALE_F * acc + 1e-8f);
    }
}

// Transpose + scale + fp16: x[b][i][l] -> x_t[b][l][i], tile 64(i) x 32(l)
__global__ void prep_xt(const float* __restrict__ x) {
    __shared__ float sm[64][33];
    const int lt = blockIdx.x;   // 0..63
    const int it = blockIdx.y;   // 0..7
    const int b  = blockIdx.z;   // 0..15
    const int warp = threadIdx.x >> 5, lane = threadIdx.x & 31;
    const int l0 = lt * 32, i0 = it * 64;
    const float* xb = x + ((size_t)b * 512) * 2048;

    #pragma unroll
    for (int r = 0; r < 8; r++) {
        int il = warp * 8 + r;
        float sv = g_s[b * 512 + i0 + il];
        sm[il][lane] = xb[(size_t)(i0 + il) * 2048 + l0 + lane] * sv;
    }
    __syncthreads();
    #pragma unroll
    for (int rr = 0; rr < 4; rr++) {
        int ll = warp * 4 + rr;
        __half2 h = __floats2half2_rn(sm[lane * 2][ll], sm[lane * 2 + 1][ll]);
        *(__half2*)(g_xt + (((size_t)b * 2048) + (l0 + ll)) * 512 + i0 + lane * 2) = h;
    }
}

// ---------------------------------------------------------------------------
// Main kernel: 1024 CTAs = 4 o x 16 l x 16 b; 256 threads (8 warps, 4m x 2n)
// warp tile 32(o) x 64(l); 16 K-chunks of 32 i x 3 taps, double-buffered.
// ---------------------------------------------------------------------------
__global__ void __launch_bounds__(NTHREADS, 2)
conv_main(float* __restrict__ out) {
    extern __shared__ char smem[];
    const uint32_t sb = smem_u32(smem);

    const int tid  = threadIdx.x;
    const int warp = tid >> 5;
    const int lane = tid & 31;
    const int mw = (warp & 3) * 32;
    const int nw = (warp >> 2) * 64;

    const int bx    = blockIdx.x;
    const int obase = (bx & 3) * 128;
    const int l0    = ((bx >> 2) & 15) * 128;
    const int b     = bx >> 6;

    // per-lane ldmatrix address components
    const uint32_t aoff = (uint32_t)(mw + (lane & 15)) * 80 + ((lane & 16) ? 16u : 0u);
    const uint32_t boff = X_OFF + (uint32_t)(nw + (lane & 7) + ((lane >> 4) << 3)) * 80
                        + ((lane & 8) ? 16u : 0u);

    const __half* xt = g_xt + ((size_t)b * 2048) * 512;
    const __half* wh = g_wh + (size_t)obase * 512;

    float acc[2][8][4];
    #pragma unroll
    for (int mi = 0; mi < 2; mi++)
        #pragma unroll
        for (int ni = 0; ni < 8; ni++)
            #pragma unroll
            for (int j = 0; j < 4; j++) acc[mi][ni][j] = 0.f;

    // ---- cp.async stage loader ----
    auto issue = [&](int ic, int sbuf) {
        uint32_t base = sbuf ? sb + STAGE : sb;
        // A: 3 taps x 128 rows x 64B = 1536 x 16B ops
        {
            int idx = tid;
            #pragma unroll
            for (int itr = 0; itr < 2; itr++) {
                int o = idx >> 2, c = idx & 3;
                const __half* s0 = wh + (size_t)o * 512 + ic * 32 + c * 8;
                uint32_t d = base + o * 80 + c * 16;
                cp16(d,             s0);
                cp16(d + A_TAP,     s0 + 262144);
                cp16(d + 2 * A_TAP, s0 + 2 * 262144);
                idx += 256;
            }
        }
        // X: 130 rows x 64B = 520 x 16B ops (rows are l0-1 .. l0+128)
        {
            int idx = tid;
            #pragma unroll
            for (int itr = 0; itr < 3; itr++) {
                if (idx < 520) {
                    int row = idx >> 2, c = idx & 3;
                    int l = l0 - 1 + row;
                    int ok = (l >= 0 && l < 2048) ? 16 : 0;
                    const __half* s1 = xt + (size_t)l * 512 + ic * 32 + c * 8;
                    cp16z(base + X_OFF + row * 80 + c * 16, s1, ok);
                }
                idx += 256;
            }
        }
        asm volatile("cp.async.commit_group;");
    };

    issue(0, 0);
    asm volatile("cp.async.wait_group 0;" ::: "memory");
    __syncthreads();

    for (int ic = 0; ic < 16; ic++) {
        if (ic < 15) issue(ic + 1, (ic + 1) & 1);

        const uint32_t base  = (ic & 1) ? sb + STAGE : sb;
        const uint32_t abase = base + aoff;
        const uint32_t bbase = base + boff;

        #pragma unroll
        for (int t = 0; t < 3; t++) {
            #pragma unroll
            for (int ks = 0; ks < 2; ks++) {
                uint32_t a0[4], a1[4];
                ldsm4(a0, abase + t * A_TAP + ks * 32);
                ldsm4(a1, abase + t * A_TAP + 16 * 80 + ks * 32);
                #pragma unroll
                for (int np = 0; np < 4; np++) {
                    uint32_t bf[4];
                    ldsm4(bf, bbase + (np * 16 + t) * 80 + ks * 32);
                    mma_f16(acc[0][np * 2],     a0, bf[0], bf[1]);
                    mma_f16(acc[1][np * 2],     a1, bf[0], bf[1]);
                    mma_f16(acc[0][np * 2 + 1], a0, bf[2], bf[3]);
                    mma_f16(acc[1][np * 2 + 1], a1, bf[2], bf[3]);
                }
            }
        }

        asm volatile("cp.async.wait_group 0;" ::: "memory");
        __syncthreads();
    }

    // ---- epilogue: apply gain, store ----
    {
        const int r0 = obase + mw + (lane >> 2);
        const float g00 = g_gain[b * 512 + r0];
        const float g01 = g_gain[b * 512 + r0 + 8];
        const float g10 = g_gain[b * 512 + r0 + 16];
        const float g11 = g_gain[b * 512 + r0 + 24];
        const int lcol = l0 + nw + (lane & 3) * 2;

        #pragma unroll
        for (int mi = 0; mi < 2; mi++) {
            const int ra = r0 + mi * 16;
            const float ga = mi ? g10 : g00;
            const float gb = mi ? g11 : g01;
            float* outa = out + ((size_t)(b * 512 + ra)) * 2048 + lcol;
            float* outb = out + ((size_t)(b * 512 + ra + 8)) * 2048 + lcol;
            #pragma unroll
            for (int ni = 0; ni < 8; ni++) {
                float2 va, vb;
                va.x = acc[mi][ni][0] * ga;
                va.y = acc[mi][ni][1] * ga;
                vb.x = acc[mi][ni][2] * gb;
                vb.y = acc[mi][ni][3] * gb;
                *(float2*)(outa + ni * 8) = va;
                *(float2*)(outb + ni * 8) = vb;
            }
        }
    }
}

// ---------------------------------------------------------------------------
extern "C" void kernel_launch(void* const* d_in, const int* in_sizes, int n_in,
                              void* d_out, int out_size) {
    const float* x      = (const float*)d_in[0];
    const float* style  = (const float*)d_in[1];
    const float* weight = (const float*)d_in[2];
    const float* modw   = (const float*)d_in[3];
    const float* bias   = (const float*)d_in[4];
    float* out = (float*)d_out;

    cudaFuncSetAttribute(conv_main, cudaFuncAttributeMaxDynamicSharedMemorySize, SMEM_TOTAL);

    prep_s<<<dim3(16, 8), 256>>>(style, modw, bias);
    prep_w<<<1024, 256>>>(weight);
    prep_gain<<<dim3(16, 8), 256>>>();
    prep_xt<<<dim3(64, 8, 16), 256>>>(x);
    conv_main<<<1024, NTHREADS, SMEM_TOTAL>>>(out);
}